// round 2
// baseline (speedup 1.0000x reference)
#include <cuda_runtime.h>

#define BN 65536
#define CN 128
#define DN 32
#define KN 10
#define DE 33            // extended dim (z, 1)
#define PSTRIDE 612      // padded packed upper-triangle size of 33x33
#define EPSV 1e-12f

// Packed per-cluster quadratic forms: for each c, rows d=0..32 of the upper
// triangle of M_c, diagonal pre-scaled by 0.5, each row zero-padded so it
// starts on a float4 boundary. 128 * 612 * 4B = 313 KB (L2-resident scratch).
__device__ float g_P[CN * PSTRIDE];

__host__ __device__ __forceinline__ int padlen_f(int d) { return ((36 - d) >> 2) << 2; }

// ---------------------------------------------------------------------------
// Pre-kernel: build M_c = [[W, -W mu],[-mu'W, mu'W mu]] packed upper triangle.
// grid = 128 (one block per cluster), block = 64.
// ---------------------------------------------------------------------------
__global__ void pre_kernel(const float* __restrict__ mu,
                           const float* __restrict__ S_inv) {
    int c = blockIdx.x;
    int t = threadIdx.x;
    __shared__ float sSm[DN];
    __shared__ float sT3;
    const float* W = S_inv + (size_t)c * DN * DN;
    const float* m = mu + (size_t)c * DN;

    if (t < DN) {
        float acc = 0.f;
        #pragma unroll
        for (int e = 0; e < DN; ++e) acc = fmaf(W[t * DN + e], m[e], acc);
        sSm[t] = acc;                       // Sm[d] = (W mu)_d
    }
    __syncthreads();
    if (t == 0) {
        float acc = 0.f;
        #pragma unroll
        for (int d = 0; d < DN; ++d) acc = fmaf(m[d], sSm[d], acc);
        sT3 = acc;                          // mu' W mu
    }
    __syncthreads();

    if (t < DE) {
        int d = t;
        int rowstart = 0;
        for (int i = 0; i < d; ++i) rowstart += padlen_f(i);
        int pl = padlen_f(d);
        float* dst = g_P + (size_t)c * PSTRIDE + rowstart;
        for (int j = 0; j < pl; ++j) {
            int e = d + j;
            float v = 0.f;
            if (e < DE) {
                if (e < DN)        v = W[d * DN + e];   // d <= e < 32
                else if (d < DN)   v = -sSm[d];          // e == 32, d < 32
                else               v = sT3;              // d == e == 32
                if (e == d)        v *= 0.5f;            // halve diagonal
            }
            dst[j] = v;
        }
    }
}

// ---------------------------------------------------------------------------
// Main kernel: one thread = one sample. For each cluster c:
//   halfq = sum_{d<=e} P[c][d,e] * z_d * z_e   (diag already halved)
//   Gamma = exp(-halfq)   (== exp(-0.5 * d2))
// Accumulate per-label score sums, running sum, running argmax.
// Cluster coefficients double-buffered through shared memory.
// ---------------------------------------------------------------------------
__global__ __launch_bounds__(256, 2)
void egauss_main(const float* __restrict__ data,
                 const int* __restrict__ labels,
                 float* __restrict__ out,
                 int out_size) {
    __shared__ float sP[2][PSTRIDE];
    __shared__ int scls[CN];

    int tid = threadIdx.x;

    // cluster -> label index (one-hot rows)
    if (tid < CN) {
        const int* row = labels + tid * KN;
        int kc = 0;
        #pragma unroll
        for (int k = 0; k < KN; ++k) if (row[k] != 0) kc = k;
        scls[tid] = kc;
    }

    // balanced sample assignment: covers b in [0, BN) exactly once with grid=296
    long b = (long)blockIdx.x + (long)gridDim.x * tid;
    bool active = b < BN;

    float z[36];
    #pragma unroll
    for (int i = 0; i < 8; ++i) {
        float4 v = make_float4(0.f, 0.f, 0.f, 0.f);
        if (active) v = ((const float4*)(data + b * DN))[i];
        z[4 * i + 0] = v.x; z[4 * i + 1] = v.y;
        z[4 * i + 2] = v.z; z[4 * i + 3] = v.w;
    }
    z[32] = 1.f; z[33] = 0.f; z[34] = 0.f; z[35] = 0.f;

    // stage cluster 0
    bool have = tid < (PSTRIDE / 4);   // 153 float4 per cluster
    if (have) {
        float4 v = ((const float4*)g_P)[tid];
        ((float4*)sP[0])[tid] = v;
    }
    __syncthreads();

    float scores[KN];
    #pragma unroll
    for (int k = 0; k < KN; ++k) scores[k] = 0.f;
    float gsum = 0.f, gbest = -1.f;
    int cbest = 0;

    for (int c = 0; c < CN; ++c) {
        int cur = c & 1;

        // prefetch next cluster's coefficients (L2 hit, hidden under FMA block)
        float4 st = make_float4(0.f, 0.f, 0.f, 0.f);
        bool pf = have && (c + 1 < CN);
        if (pf) st = ((const float4*)(g_P + (size_t)(c + 1) * PSTRIDE))[tid];

        // halfq = z' M z / 2 via packed upper triangle
        float halfq = 0.f;
        {
            const float* p = sP[cur];
            int off = 0;
            #pragma unroll
            for (int d = 0; d < DE; ++d) {
                const int pl = ((36 - d) >> 2) << 2;
                float acc = 0.f;
                #pragma unroll
                for (int j = 0; j < pl; ++j)
                    acc = fmaf(p[off + j], z[d + j], acc);
                halfq = fmaf(z[d], acc, halfq);
                off += pl;
            }
        }

        float g = expf(-halfq);
        gsum += g;
        if (g > gbest) { gbest = g; cbest = c; }   // strict > == first-max (jnp)
        int kc = scls[c];
        #pragma unroll
        for (int k = 0; k < KN; ++k)
            if (kc == k) scores[k] += g;

        if (pf) ((float4*)sP[cur ^ 1])[tid] = st;
        __syncthreads();
    }

    if (active) {
        float inv = 1.f / (gsum + EPSV);
        float sbest = -1.f;
        int pbest = 0;
        float* os = out + b * KN;
        #pragma unroll
        for (int k = 0; k < KN; ++k) {
            float s = scores[k] * inv;
            os[k] = s;
            if (s > sbest) { sbest = s; pbest = k; }   // first-max tie-break
        }
        // preds / clusters as float, guarded by out_size (layout: scores | preds | clusters)
        long base = (long)BN * KN;
        if (out_size >= base + BN)       out[base + b] = (float)pbest;
        if (out_size >= base + 2 * BN)   out[base + BN + b] = (float)cbest;
    }
}

extern "C" void kernel_launch(void* const* d_in, const int* in_sizes, int n_in,
                              void* d_out, int out_size) {
    const float* data   = (const float*)d_in[0];
    const float* mu     = (const float*)d_in[1];
    const float* S_inv  = (const float*)d_in[2];
    const int*   labels = (const int*)d_in[3];

    pre_kernel<<<CN, 64>>>(mu, S_inv);
    egauss_main<<<296, 256>>>(data, labels, (float*)d_out, out_size);
}